// round 2
// baseline (speedup 1.0000x reference)
#include <cuda_runtime.h>

// DfOp: out[b,t,f] = sum_{i=0..4} spec[b, t+i-4, f] * coefs[b, i, t, f]  (complex)  for f < 96
//       out[b,t,f] = spec[b,t,f]                                                   for f >= 96
// spec:  (8, 1, 4096, 481, 2) f32   -> float2 view, idx = (b*T + t)*F + f
// coefs: (8, 5, 4096,  96, 2) f32   -> float2 view, idx = ((b*5 + i)*T + t)*NF + f

#define DF_B  8
#define DF_T  4096
#define DF_F  481
#define DF_NF 96
#define DF_FS 5

__global__ __launch_bounds__(256) void df_op_kernel(
    const float2* __restrict__ spec,
    const float2* __restrict__ coefs,
    float2* __restrict__ out,
    int total)
{
    int idx = blockIdx.x * blockDim.x + threadIdx.x;
    if (idx >= total) return;

    int f  = idx % DF_F;
    int bt = idx / DF_F;          // b*T + t

    if (f >= DF_NF) {
        // passthrough copy of high-frequency bins
        out[idx] = spec[idx];
        return;
    }

    int t = bt % DF_T;
    int b = bt / DF_T;

    // coefs base for (b, i=0, t, f)
    const float2* __restrict__ cptr = coefs + ((long)b * DF_FS * DF_T + t) * DF_NF + f;
    // spec base for (b, t, f) — history rows are at negative F strides
    const float2* __restrict__ sptr = spec + (long)bt * DF_F + f;

    float re = 0.f, im = 0.f;
    #pragma unroll
    for (int i = 0; i < DF_FS; i++) {
        int ts = t + i - (DF_FS - 1);           // source time index
        if (ts >= 0) {
            float2 c = cptr[(long)i * DF_T * DF_NF];
            float2 s = sptr[(long)(i - (DF_FS - 1)) * DF_F];
            re = fmaf(s.x, c.x, re);
            re = fmaf(-s.y, c.y, re);
            im = fmaf(s.x, c.y, im);
            im = fmaf(s.y, c.x, im);
        }
    }
    out[idx] = make_float2(re, im);
}

extern "C" void kernel_launch(void* const* d_in, const int* in_sizes, int n_in,
                              void* d_out, int out_size)
{
    const float2* spec  = (const float2*)d_in[0];
    const float2* coefs = (const float2*)d_in[1];
    float2* out = (float2*)d_out;

    int total = DF_B * DF_T * DF_F;   // 15,761,408 complex outputs
    int threads = 256;
    int blocks = (total + threads - 1) / threads;
    df_op_kernel<<<blocks, threads>>>(spec, coefs, out, total);
}

// round 3
// speedup vs baseline: 1.0301x; 1.0301x over previous
#include <cuda_runtime.h>

// DfOp: out[b,t,f] = sum_{i=0..4} spec[b, t+i-4, f] * coefs[b, i, t, f]  (complex) for f < 96
//       out[b,t,f] = spec[b,t,f]                                                  for f >= 96
// spec:  (8, 1, 4096, 481, 2) f32   -> float2 view, idx = (b*T + t)*F + f
// coefs: (8, 5, 4096,  96, 2) f32   -> float2 view, idx = ((b*5 + i)*T + t)*NF + f
//
// Layout: one block per (b,t) row. 256 threads; thread handles f = tid and f = tid+256.
//  - no integer div/mod (T is power of 2)
//  - interior rows (t >= 4): branch-free, 10 unconditional front-batched LDGs
//  - streaming hints: coefs (__ldcs, read once), spec-hi (__ldcs, read once),
//    all stores (__stcs, never re-read) -> keeps L2 free for the spec-lo reuse window

#define DF_B  8
#define DF_T  4096
#define DF_F  481
#define DF_NF 96
#define DF_FS 5

__global__ __launch_bounds__(256) void df_op_kernel(
    const float2* __restrict__ spec,
    const float2* __restrict__ coefs,
    float2* __restrict__ out)
{
    const int bt  = blockIdx.x;          // 0 .. B*T-1
    const int t   = bt & (DF_T - 1);
    const int b   = bt >> 12;            // log2(4096)
    const int tid = threadIdx.x;

    const long rowbase = (long)bt * DF_F;
    const float2* __restrict__ srow = spec + rowbase;
    float2* __restrict__       orow = out  + rowbase;

    // ---- element 1: f = tid (filter for f<96, copy otherwise) ----
    const int f = tid;
    if (f < DF_NF) {
        const float2* __restrict__ cptr =
            coefs + ((long)b * DF_FS * DF_T + t) * DF_NF + f;
        const float2* __restrict__ sptr = srow + f;

        float re = 0.f, im = 0.f;
        if (t >= DF_FS - 1) {
            // interior: unconditional taps, loads batch at interval start
            #pragma unroll
            for (int i = 0; i < DF_FS; i++) {
                float2 c = __ldcs(cptr + (long)i * DF_T * DF_NF);
                float2 s = sptr[(long)(i - (DF_FS - 1)) * DF_F];
                re = fmaf( s.x, c.x, re);
                re = fmaf(-s.y, c.y, re);
                im = fmaf( s.x, c.y, im);
                im = fmaf( s.y, c.x, im);
            }
        } else {
            // first 4 time steps: guarded taps
            #pragma unroll
            for (int i = 0; i < DF_FS; i++) {
                if (t + i >= DF_FS - 1) {
                    float2 c = __ldcs(cptr + (long)i * DF_T * DF_NF);
                    float2 s = sptr[(long)(i - (DF_FS - 1)) * DF_F];
                    re = fmaf( s.x, c.x, re);
                    re = fmaf(-s.y, c.y, re);
                    im = fmaf( s.x, c.y, im);
                    im = fmaf( s.y, c.x, im);
                }
            }
        }
        __stcs(orow + f, make_float2(re, im));
    } else {
        __stcs(orow + f, __ldcs(srow + f));
    }

    // ---- element 2: f2 = tid + 256 (always passthrough copy) ----
    const int f2 = tid + 256;
    if (f2 < DF_F) {
        __stcs(orow + f2, __ldcs(srow + f2));
    }
}

extern "C" void kernel_launch(void* const* d_in, const int* in_sizes, int n_in,
                              void* d_out, int out_size)
{
    const float2* spec  = (const float2*)d_in[0];
    const float2* coefs = (const float2*)d_in[1];
    float2* out = (float2*)d_out;

    dim3 grid(DF_B * DF_T);   // 32768 blocks, one per (b,t) row
    df_op_kernel<<<grid, 256>>>(spec, coefs, out);
}

// round 5
// speedup vs baseline: 1.1699x; 1.1357x over previous
#include <cuda_runtime.h>

// DfOp: out[b,t,f] = sum_{i=0..4} spec[b, t+i-4, f] * coefs[b, i, t, f]  (complex) for f < 96
//       out[b,t,f] = spec[b,t,f]                                                  for f >= 96
// spec:  (8, 1, 4096, 481, 2) f32, coefs: (8, 5, 4096, 96, 2) f32
//
// Block = 128 threads, one (b,t) row per block.
//   warps 0-2 (tid 0..95):  filter output f=tid (10 front-batched LDG.64)
//   warp 3   (tid 96..127): copy region floats [192,962) as 1 float2 + 192 float4
//                           (row base alternates 16B alignment; f4_start = 192+2*(bt&1))

#define DF_B  8
#define DF_T  4096
#define DF_F  481
#define DF_NF 96
#define DF_FS 5
#define ROW_FLOATS (2 * DF_F)   // 962

__global__ __launch_bounds__(128) void df_op_kernel(
    const float* __restrict__ specf,
    const float2* __restrict__ coefs,
    float* __restrict__ outf)
{
    const int bt  = blockIdx.x;           // 0 .. B*T-1
    const int t   = bt & (DF_T - 1);
    const int b   = bt >> 12;
    const int tid = threadIdx.x;
    const long rowf = (long)bt * ROW_FLOATS;   // float offset of row base

    if (tid < DF_NF) {
        // ---------------- filter path: f = tid ----------------
        const float2* __restrict__ srow = (const float2*)specf + (long)bt * DF_F;
        const float2* __restrict__ cptr =
            coefs + ((long)b * DF_FS * DF_T + t) * DF_NF + tid;
        const float2* __restrict__ sptr = srow + tid;

        float re = 0.f, im = 0.f;
        if (t >= DF_FS - 1) {
            #pragma unroll
            for (int i = 0; i < DF_FS; i++) {
                float2 c = __ldcs(cptr + (long)i * DF_T * DF_NF);
                float2 s = sptr[(long)(i - (DF_FS - 1)) * DF_F];
                re = fmaf( s.x, c.x, re);
                re = fmaf(-s.y, c.y, re);
                im = fmaf( s.x, c.y, im);
                im = fmaf( s.y, c.x, im);
            }
        } else {
            #pragma unroll
            for (int i = 0; i < DF_FS; i++) {
                if (t + i >= DF_FS - 1) {
                    float2 c = __ldcs(cptr + (long)i * DF_T * DF_NF);
                    float2 s = sptr[(long)(i - (DF_FS - 1)) * DF_F];
                    re = fmaf( s.x, c.x, re);
                    re = fmaf(-s.y, c.y, re);
                    im = fmaf( s.x, c.y, im);
                    im = fmaf( s.y, c.x, im);
                }
            }
        }
        __stcs((float2*)outf + (long)bt * DF_F + tid, make_float2(re, im));
    } else {
        // ---------------- copy path: floats [192, 962) of this row ----------------
        const int  j   = tid - DF_NF;          // 0..31
        const int  odd = bt & 1;
        const long f4base = rowf + 192 + 2 * odd;   // (rowf + f4base) % 4 == 0

        const float4* __restrict__ src = (const float4*)(specf + f4base);
        float4* __restrict__       dst = (float4*)(outf + f4base);

        // 6 float4s per thread, warp-coalesced, front-batched for MLP
        float4 v0 = __ldcs(src + j);
        float4 v1 = __ldcs(src + j + 32);
        float4 v2 = __ldcs(src + j + 64);
        float4 v3 = __ldcs(src + j + 96);
        float4 v4 = __ldcs(src + j + 128);
        float4 v5 = __ldcs(src + j + 160);
        __stcs(dst + j,       v0);
        __stcs(dst + j + 32,  v1);
        __stcs(dst + j + 64,  v2);
        __stcs(dst + j + 96,  v3);
        __stcs(dst + j + 128, v4);
        __stcs(dst + j + 160, v5);

        // leftover float2: even rows at float 960, odd rows at float 192
        if (j == 0) {
            const long f2off = rowf + (odd ? 192 : 960);
            float2 v = __ldcs((const float2*)(specf + f2off));
            __stcs((float2*)(outf + f2off), v);
        }
    }
}

extern "C" void kernel_launch(void* const* d_in, const int* in_sizes, int n_in,
                              void* d_out, int out_size)
{
    const float*  spec  = (const float*)d_in[0];
    const float2* coefs = (const float2*)d_in[1];
    float* out = (float*)d_out;

    df_op_kernel<<<DF_B * DF_T, 128>>>(spec, coefs, out);
}

// round 6
// speedup vs baseline: 1.1909x; 1.0179x over previous
#include <cuda_runtime.h>

// DfOp: out[b,t,f] = sum_{i=0..4} spec[b, t+i-4, f] * coefs[b, i, t, f] (complex) for f < 96
//       out[b,t,f] = spec[b,t,f]                                                 for f >= 96
// spec:  (8, 1, 4096, 481, 2) f32, coefs: (8, 5, 4096, 96, 2) f32
//
// Block = 128 threads handles TWO consecutive rows (r0 = 2*bid even, r1 odd).
//  tid 0..47  : filter row r0, bins 2j,2j+1 — 5x LDG.128 coef + 10x LDG.64 spec (160 B in flight)
//  tid 48..95 : filter row r1, same
//  tid 96..127: copy float region [192,962) of both rows — 12x LDG.128 (192 B in flight)

#define DF_B  8
#define DF_T  4096
#define DF_F  481
#define DF_NF 96
#define DF_FS 5
#define ROW_FLOATS (2 * DF_F)   // 962

__global__ __launch_bounds__(128) void df_op_kernel(
    const float* __restrict__ specf,
    const float4* __restrict__ coefs4,   // coefs viewed as float4 = 2 complex bins
    float* __restrict__ outf)
{
    const int bid = blockIdx.x;
    const int r0  = bid << 1;            // even row
    const int tid = threadIdx.x;

    if (tid < 96) {
        // ---------------- filter path: 2 bins per thread ----------------
        const int row = r0 + (tid >= 48);
        const int j   = (tid >= 48) ? tid - 48 : tid;   // 0..47 -> bins 2j, 2j+1
        const int t   = row & (DF_T - 1);
        const int b   = row >> 12;
        const long rowf = (long)row * ROW_FLOATS;

        // coefs float4 index for (b, i, t, bin-pair j): ((b*5+i)*T + t)*48 + j
        const int cbase = ((b * DF_FS) * DF_T + t) * 48 + j;
        const float* __restrict__ sp = specf + rowf + 4 * j;  // bin 2j at +0, 2j+1 at +2

        float re0 = 0.f, im0 = 0.f, re1 = 0.f, im1 = 0.f;
        if (t >= DF_FS - 1) {
            #pragma unroll
            for (int i = 0; i < DF_FS; i++) {
                float4 c = __ldcs(coefs4 + cbase + i * (DF_T * 48));
                const float* s = sp + (long)(i - (DF_FS - 1)) * ROW_FLOATS;
                float2 sa = *(const float2*)(s);
                float2 sb = *(const float2*)(s + 2);
                re0 = fmaf( sa.x, c.x, re0); re0 = fmaf(-sa.y, c.y, re0);
                im0 = fmaf( sa.x, c.y, im0); im0 = fmaf( sa.y, c.x, im0);
                re1 = fmaf( sb.x, c.z, re1); re1 = fmaf(-sb.y, c.w, re1);
                im1 = fmaf( sb.x, c.w, im1); im1 = fmaf( sb.y, c.z, im1);
            }
        } else {
            #pragma unroll
            for (int i = 0; i < DF_FS; i++) {
                if (t + i >= DF_FS - 1) {
                    float4 c = __ldcs(coefs4 + cbase + i * (DF_T * 48));
                    const float* s = sp + (long)(i - (DF_FS - 1)) * ROW_FLOATS;
                    float2 sa = *(const float2*)(s);
                    float2 sb = *(const float2*)(s + 2);
                    re0 = fmaf( sa.x, c.x, re0); re0 = fmaf(-sa.y, c.y, re0);
                    im0 = fmaf( sa.x, c.y, im0); im0 = fmaf( sa.y, c.x, im0);
                    re1 = fmaf( sb.x, c.z, re1); re1 = fmaf(-sb.y, c.w, re1);
                    im1 = fmaf( sb.x, c.w, im1); im1 = fmaf( sb.y, c.z, im1);
                }
            }
        }
        __stcs((float2*)(outf + rowf + 4 * j),     make_float2(re0, im0));
        __stcs((float2*)(outf + rowf + 4 * j + 2), make_float2(re1, im1));
    } else {
        // ---------------- copy path: both rows, floats [192,962) ----------------
        const int j = tid - 96;                       // 0..31
        const long rf0 = (long)r0 * ROW_FLOATS;       // even row: %4 == 0
        const long rf1 = rf0 + ROW_FLOATS;            // odd row:  %4 == 2

        const float4* __restrict__ s0 = (const float4*)(specf + rf0 + 192); // aligned
        const float4* __restrict__ s1 = (const float4*)(specf + rf1 + 194); // aligned
        float4* __restrict__ d0 = (float4*)(outf + rf0 + 192);
        float4* __restrict__ d1 = (float4*)(outf + rf1 + 194);

        // 12 front-batched LDG.128 per thread
        float4 a0 = __ldcs(s0 + j);
        float4 a1 = __ldcs(s0 + j + 32);
        float4 a2 = __ldcs(s0 + j + 64);
        float4 a3 = __ldcs(s0 + j + 96);
        float4 a4 = __ldcs(s0 + j + 128);
        float4 a5 = __ldcs(s0 + j + 160);
        float4 b0 = __ldcs(s1 + j);
        float4 b1 = __ldcs(s1 + j + 32);
        float4 b2 = __ldcs(s1 + j + 64);
        float4 b3 = __ldcs(s1 + j + 96);
        float4 b4 = __ldcs(s1 + j + 128);
        float4 b5 = __ldcs(s1 + j + 160);

        __stcs(d0 + j,       a0);
        __stcs(d0 + j + 32,  a1);
        __stcs(d0 + j + 64,  a2);
        __stcs(d0 + j + 96,  a3);
        __stcs(d0 + j + 128, a4);
        __stcs(d0 + j + 160, a5);
        __stcs(d1 + j,       b0);
        __stcs(d1 + j + 32,  b1);
        __stcs(d1 + j + 64,  b2);
        __stcs(d1 + j + 96,  b3);
        __stcs(d1 + j + 128, b4);
        __stcs(d1 + j + 160, b5);

        // leftover float2s: even row at +960, odd row at +192
        if (j == 0) {
            float2 v = __ldcs((const float2*)(specf + rf0 + 960));
            __stcs((float2*)(outf + rf0 + 960), v);
        } else if (j == 1) {
            float2 v = __ldcs((const float2*)(specf + rf1 + 192));
            __stcs((float2*)(outf + rf1 + 192), v);
        }
    }
}

extern "C" void kernel_launch(void* const* d_in, const int* in_sizes, int n_in,
                              void* d_out, int out_size)
{
    const float*  spec   = (const float*)d_in[0];
    const float4* coefs4 = (const float4*)d_in[1];
    float* out = (float*)d_out;

    df_op_kernel<<<(DF_B * DF_T) / 2, 128>>>(spec, coefs4, out);
}